// round 1
// baseline (speedup 1.0000x reference)
#include <cuda_runtime.h>
#include <math.h>

// ---------------------------------------------------------------------------
// Scratch (device globals — no allocation allowed)
// ---------------------------------------------------------------------------
__device__ float g_w1[64 * 25];
__device__ float g_b1[64];
__device__ float g_w2[64 * 64 * 25];
__device__ float g_b2[64];
__device__ float g_w3[10 * 1024];
__device__ float g_b3[10];
__device__ float g_pool1[(size_t)2048 * 64 * 144];  // 75.5 MB
__device__ float g_pool2[(size_t)2048 * 1024];      // 8.4 MB
__device__ float g_smax1[2048];
__device__ float g_max2[2048 * 64];
__device__ float g_stat1;
__device__ float g_stat2[64];
__device__ float g_stat3[1024];

// ---------------------------------------------------------------------------
// Helpers
// ---------------------------------------------------------------------------
__device__ __forceinline__ float warp_max(float v) {
    #pragma unroll
    for (int o = 16; o; o >>= 1) v = fmaxf(v, __shfl_xor_sync(0xFFFFFFFFu, v, o));
    return v;
}
__device__ __forceinline__ float warp_sum(float v) {
    #pragma unroll
    for (int o = 16; o; o >>= 1) v += __shfl_xor_sync(0xFFFFFFFFu, v, o);
    return v;
}

__device__ __forceinline__ float scinol_p(float p0, float S2, float G, float eta,
                                          float M, bool cond) {
    float denom = sqrtf(S2 + M * M);
    float theta = fminf(fmaxf(G / denom, -1.0f), 1.0f);
    float upd = cond ? theta / (2.0f * denom) * eta : 0.0f;
    return p0 + upd;
}

// ---------------------------------------------------------------------------
// Stage 1: stat1 = mean_n( max_{h,w} |x[n,0,h,w]| )
// ---------------------------------------------------------------------------
__global__ void k_stat1_max(const float* __restrict__ x) {
    int n = blockIdx.x;
    const float* xp = x + (size_t)n * 784;
    float m = 0.0f;
    for (int i = threadIdx.x; i < 784; i += 256) m = fmaxf(m, fabsf(xp[i]));
    __shared__ float s[8];
    m = warp_max(m);
    if ((threadIdx.x & 31) == 0) s[threadIdx.x >> 5] = m;
    __syncthreads();
    if (threadIdx.x < 32) {
        float v = (threadIdx.x < 8) ? s[threadIdx.x] : 0.0f;
        v = warp_max(v);
        if (threadIdx.x == 0) g_smax1[n] = v;
    }
}

__global__ void k_stat1_mean() {
    float s = 0.0f;
    for (int i = threadIdx.x; i < 2048; i += 256) s += g_smax1[i];
    __shared__ float sm[8];
    s = warp_sum(s);
    if ((threadIdx.x & 31) == 0) sm[threadIdx.x >> 5] = s;
    __syncthreads();
    if (threadIdx.x < 32) {
        float v = (threadIdx.x < 8) ? sm[threadIdx.x] : 0.0f;
        v = warp_sum(v);
        if (threadIdx.x == 0) g_stat1 = v * (1.0f / 2048.0f);
    }
}

// ---------------------------------------------------------------------------
// Conv1 effective weights (cond: wG != 0 / bG != 0; M = max(stat1, wM[0]))
// ---------------------------------------------------------------------------
__global__ void k_w1(const float* __restrict__ w0, const float* __restrict__ wS2,
                     const float* __restrict__ wG, const float* __restrict__ weta,
                     const float* __restrict__ wM,
                     const float* __restrict__ b0, const float* __restrict__ bS2,
                     const float* __restrict__ bG, const float* __restrict__ beta) {
    float M = fmaxf(g_stat1, wM[0]);
    int tot = gridDim.x * blockDim.x;
    int gid = blockIdx.x * blockDim.x + threadIdx.x;
    for (int i = gid; i < 1600; i += tot)
        g_w1[i] = scinol_p(w0[i], wS2[i], wG[i], weta[i], M, wG[i] != 0.0f);
    for (int i = gid; i < 64; i += tot)
        g_b1[i] = scinol_p(b0[i], bS2[i], bG[i], beta[i], 1.0f, bG[i] != 0.0f);
}

// ---------------------------------------------------------------------------
// Conv1 + ReLU + 2x2 maxpool, fused; writes pool1 and per-(n,c) plane max.
// Block = one sample. 256 threads: channel c = tid>>2, 4 threads share channel,
// each owns 9 of the 36 (4x4-conv -> 2x2-pooled) tiles. Register-tiled.
// ---------------------------------------------------------------------------
__global__ void __launch_bounds__(256, 2) k_conv1(const float* __restrict__ x) {
    __shared__ float xs[784];
    __shared__ float ws[1600];
    __shared__ float bs[64];
    int n = blockIdx.x;
    int tid = threadIdx.x;
    const float* xp = x + (size_t)n * 784;
    for (int i = tid; i < 784; i += 256) xs[i] = xp[i];
    for (int i = tid; i < 1600; i += 256) ws[i] = g_w1[i];
    if (tid < 64) bs[tid] = g_b1[tid];
    __syncthreads();

    int c = tid >> 2, q = tid & 3;
    const float* wc = ws + c * 25;
    float b = bs[c];
    float cmax = 0.0f;
    float* outp = g_pool1 + ((size_t)n * 64 + c) * 144;

    for (int t = q; t < 36; t += 4) {
        int tr = t / 6, tc = t - tr * 6;
        int by = tr * 4, bx = tc * 4;
        float xin[8][8];
        #pragma unroll
        for (int r = 0; r < 8; r++)
            #pragma unroll
            for (int cc = 0; cc < 8; cc++)
                xin[r][cc] = xs[(by + r) * 28 + bx + cc];
        float acc[4][4] = {};
        #pragma unroll
        for (int ky = 0; ky < 5; ky++)
            #pragma unroll
            for (int kx = 0; kx < 5; kx++) {
                float w = wc[ky * 5 + kx];
                #pragma unroll
                for (int i = 0; i < 4; i++)
                    #pragma unroll
                    for (int j = 0; j < 4; j++)
                        acc[i][j] = fmaf(w, xin[i + ky][j + kx], acc[i][j]);
            }
        #pragma unroll
        for (int pi = 0; pi < 2; pi++)
            #pragma unroll
            for (int pj = 0; pj < 2; pj++) {
                float m4 = fmaxf(fmaxf(acc[2 * pi][2 * pj], acc[2 * pi][2 * pj + 1]),
                                 fmaxf(acc[2 * pi + 1][2 * pj], acc[2 * pi + 1][2 * pj + 1]));
                float v = fmaxf(m4 + b, 0.0f);
                outp[(tr * 2 + pi) * 12 + (tc * 2 + pj)] = v;
                cmax = fmaxf(cmax, v);
            }
    }
    // reduce the per-channel max over the 4 threads sharing channel c
    cmax = fmaxf(cmax, __shfl_xor_sync(0xFFFFFFFFu, cmax, 1));
    cmax = fmaxf(cmax, __shfl_xor_sync(0xFFFFFFFFu, cmax, 2));
    if (q == 0) g_max2[n * 64 + c] = cmax;
}

// ---------------------------------------------------------------------------
// stat2[c] = mean_n g_max2[n][c]
// ---------------------------------------------------------------------------
__global__ void k_stat2() {
    int c = blockIdx.x;
    float s = 0.0f;
    for (int i = threadIdx.x; i < 2048; i += 256) s += g_max2[i * 64 + c];
    __shared__ float sm[8];
    s = warp_sum(s);
    if ((threadIdx.x & 31) == 0) sm[threadIdx.x >> 5] = s;
    __syncthreads();
    if (threadIdx.x < 32) {
        float v = (threadIdx.x < 8) ? sm[threadIdx.x] : 0.0f;
        v = warp_sum(v);
        if (threadIdx.x == 0) g_stat2[c] = v * (1.0f / 2048.0f);
    }
}

// ---------------------------------------------------------------------------
// Conv2 effective weights (M per input channel; cond wG!=0 / bG!=0)
// ---------------------------------------------------------------------------
__global__ void k_w2(const float* __restrict__ w0, const float* __restrict__ wS2,
                     const float* __restrict__ wG, const float* __restrict__ weta,
                     const float* __restrict__ wM,
                     const float* __restrict__ b0, const float* __restrict__ bS2,
                     const float* __restrict__ bG, const float* __restrict__ beta) {
    int tot = gridDim.x * blockDim.x;
    int gid = blockIdx.x * blockDim.x + threadIdx.x;
    for (int i = gid; i < 102400; i += tot) {
        int ci = (i / 25) & 63;   // weight layout (o, i, ky, kx)
        float M = fmaxf(g_stat2[ci], wM[ci]);
        g_w2[i] = scinol_p(w0[i], wS2[i], wG[i], weta[i], M, wG[i] != 0.0f);
    }
    for (int i = gid; i < 64; i += tot)
        g_b2[i] = scinol_p(b0[i], bS2[i], bG[i], beta[i], 1.0f, bG[i] != 0.0f);
}

// ---------------------------------------------------------------------------
// Conv2 + ReLU + 2x2 maxpool, fused. Block = one sample; smem holds the whole
// 64x12x12 input plane. 256 threads: co = tid>>2, 4 threads cover the 2x2
// arrangement of 4x4-conv tiles. Weights stream from L2/L1 (shared across the
// 4 threads of a channel and across blocks).
// ---------------------------------------------------------------------------
__global__ void __launch_bounds__(256, 2) k_conv2() {
    __shared__ float xs[9216];  // 36 KB
    int n = blockIdx.x;
    int tid = threadIdx.x;
    const float* src = g_pool1 + (size_t)n * 9216;
    for (int i = tid; i < 9216; i += 256) xs[i] = src[i];
    __syncthreads();

    int co = tid >> 2, t = tid & 3;
    int ty = t >> 1, tx = t & 1;
    float acc[4][4] = {};
    const float* wbase = g_w2 + co * 1600;
    const float* xcs0 = xs + (ty * 4) * 12 + tx * 4;

    for (int ci = 0; ci < 64; ci++) {
        float xin[8][8];
        const float* xcs = xcs0 + ci * 144;
        #pragma unroll
        for (int r = 0; r < 8; r++)
            #pragma unroll
            for (int cc = 0; cc < 8; cc++)
                xin[r][cc] = xcs[r * 12 + cc];
        const float* wp = wbase + ci * 25;
        #pragma unroll
        for (int ky = 0; ky < 5; ky++)
            #pragma unroll
            for (int kx = 0; kx < 5; kx++) {
                float w = __ldg(wp + ky * 5 + kx);
                #pragma unroll
                for (int i = 0; i < 4; i++)
                    #pragma unroll
                    for (int j = 0; j < 4; j++)
                        acc[i][j] = fmaf(w, xin[i + ky][j + kx], acc[i][j]);
            }
    }

    float b = __ldg(g_b2 + co);
    float* outp = g_pool2 + (size_t)n * 1024;
    #pragma unroll
    for (int pi = 0; pi < 2; pi++)
        #pragma unroll
        for (int pj = 0; pj < 2; pj++) {
            float m4 = fmaxf(fmaxf(acc[2 * pi][2 * pj], acc[2 * pi][2 * pj + 1]),
                             fmaxf(acc[2 * pi + 1][2 * pj], acc[2 * pi + 1][2 * pj + 1]));
            float v = fmaxf(m4 + b, 0.0f);
            int py = ty * 2 + pi, px = tx * 2 + pj;
            outp[co * 16 + py * 4 + px] = v;  // flattened (c,4,4) feature layout
        }
}

// ---------------------------------------------------------------------------
// stat3[f] = mean_n pool2[n][f]   (values are >= 0 so |.| is identity)
// blockDim (32, 8): tx = feature within block (coalesced), ty = batch slice.
// ---------------------------------------------------------------------------
__global__ void k_stat3() {
    int f = blockIdx.x * 32 + threadIdx.x;
    float s = 0.0f;
    for (int nidx = threadIdx.y; nidx < 2048; nidx += 8)
        s += g_pool2[(size_t)nidx * 1024 + f];
    __shared__ float sm[8][32];
    sm[threadIdx.y][threadIdx.x] = s;
    __syncthreads();
    if (threadIdx.y == 0) {
        float tot = 0.0f;
        #pragma unroll
        for (int r = 0; r < 8; r++) tot += sm[r][threadIdx.x];
        g_stat3[f] = tot * (1.0f / 2048.0f);
    }
}

// ---------------------------------------------------------------------------
// Linear effective weights (NOTE: cond is wS2!=0 / bS2!=0 for this layer;
// M = max(wM[o,f], stat3[f]) elementwise)
// ---------------------------------------------------------------------------
__global__ void k_w3(const float* __restrict__ w0, const float* __restrict__ wS2,
                     const float* __restrict__ wG, const float* __restrict__ weta,
                     const float* __restrict__ wM,
                     const float* __restrict__ b0, const float* __restrict__ bS2,
                     const float* __restrict__ bG, const float* __restrict__ beta) {
    int tot = gridDim.x * blockDim.x;
    int gid = blockIdx.x * blockDim.x + threadIdx.x;
    for (int i = gid; i < 10240; i += tot) {
        int f = i & 1023;
        float M = fmaxf(wM[i], g_stat3[f]);
        g_w3[i] = scinol_p(w0[i], wS2[i], wG[i], weta[i], M, wS2[i] != 0.0f);
    }
    for (int i = gid; i < 10; i += tot)
        g_b3[i] = scinol_p(b0[i], bS2[i], bG[i], beta[i], 1.0f, bS2[i] != 0.0f);
}

// ---------------------------------------------------------------------------
// Linear: out[n][o] = pool2[n] . w3[o] + b3[o]. Block = sample, warp = output.
// ---------------------------------------------------------------------------
__global__ void __launch_bounds__(320) k_linear(float* __restrict__ out) {
    __shared__ float hs[1024];
    int n = blockIdx.x;
    int tid = threadIdx.x;
    const float* src = g_pool2 + (size_t)n * 1024;
    for (int i = tid; i < 1024; i += 320) hs[i] = src[i];
    __syncthreads();
    int w = tid >> 5, lane = tid & 31;
    const float* wr = g_w3 + w * 1024;
    float s = 0.0f;
    #pragma unroll 8
    for (int k = lane; k < 1024; k += 32) s = fmaf(hs[k], wr[k], s);
    s = warp_sum(s);
    if (lane == 0) out[n * 10 + w] = s + g_b3[w];
}

// ---------------------------------------------------------------------------
// Launch
// ---------------------------------------------------------------------------
extern "C" void kernel_launch(void* const* d_in, const int* in_sizes, int n_in,
                              void* d_out, int out_size) {
    const float* x = (const float*)d_in[0];
    const float* c1_w0 = (const float*)d_in[1];
    const float* c1_wS2 = (const float*)d_in[2];
    const float* c1_wG = (const float*)d_in[3];
    const float* c1_weta = (const float*)d_in[4];
    const float* c1_wM = (const float*)d_in[5];
    const float* c1_b0 = (const float*)d_in[6];
    const float* c1_bS2 = (const float*)d_in[7];
    const float* c1_bG = (const float*)d_in[8];
    const float* c1_beta = (const float*)d_in[9];
    const float* c2_w0 = (const float*)d_in[10];
    const float* c2_wS2 = (const float*)d_in[11];
    const float* c2_wG = (const float*)d_in[12];
    const float* c2_weta = (const float*)d_in[13];
    const float* c2_wM = (const float*)d_in[14];
    const float* c2_b0 = (const float*)d_in[15];
    const float* c2_bS2 = (const float*)d_in[16];
    const float* c2_bG = (const float*)d_in[17];
    const float* c2_beta = (const float*)d_in[18];
    const float* l_w0 = (const float*)d_in[19];
    const float* l_wS2 = (const float*)d_in[20];
    const float* l_wG = (const float*)d_in[21];
    const float* l_weta = (const float*)d_in[22];
    const float* l_wM = (const float*)d_in[23];
    const float* l_b0 = (const float*)d_in[24];
    const float* l_bS2 = (const float*)d_in[25];
    const float* l_bG = (const float*)d_in[26];
    const float* l_beta = (const float*)d_in[27];
    float* out = (float*)d_out;

    k_stat1_max<<<2048, 256>>>(x);
    k_stat1_mean<<<1, 256>>>();
    k_w1<<<8, 256>>>(c1_w0, c1_wS2, c1_wG, c1_weta, c1_wM, c1_b0, c1_bS2, c1_bG, c1_beta);
    k_conv1<<<2048, 256>>>(x);
    k_stat2<<<64, 256>>>();
    k_w2<<<128, 256>>>(c2_w0, c2_wS2, c2_wG, c2_weta, c2_wM, c2_b0, c2_bS2, c2_bG, c2_beta);
    k_conv2<<<2048, 256>>>();
    k_stat3<<<32, dim3(32, 8)>>>();
    k_w3<<<48, 256>>>(l_w0, l_wS2, l_wG, l_weta, l_wM, l_b0, l_bS2, l_bG, l_beta);
    k_linear<<<2048, 320>>>(out);
}

// round 2
// speedup vs baseline: 1.5605x; 1.5605x over previous
#include <cuda_runtime.h>
#include <math.h>

typedef unsigned long long ull;

// ---------------------------------------------------------------------------
// Scratch (device globals — no allocation allowed)
// ---------------------------------------------------------------------------
__device__ ull   g_w1p[25 * 32];          // packed conv1 weights [k][coP] -> (w[2c],w[2c+1])
__device__ float g_b1[64];
__device__ ull   g_w2p[64 * 25 * 32];     // packed conv2 weights [ci][k][coP]
__device__ float g_b2[64];
__device__ float g_w3[10 * 1024];
__device__ float g_b3[10];
__device__ float g_pool1[(size_t)2048 * 64 * 144];  // 75.5 MB
__device__ float g_pool2[(size_t)2048 * 1024];      // 8.4 MB
__device__ float g_smax1[2048];
__device__ float g_max2[2048 * 64];
__device__ float g_stat1;
__device__ float g_stat2[64];
__device__ float g_stat3[1024];

// ---------------------------------------------------------------------------
// Helpers
// ---------------------------------------------------------------------------
__device__ __forceinline__ float warp_max(float v) {
    #pragma unroll
    for (int o = 16; o; o >>= 1) v = fmaxf(v, __shfl_xor_sync(0xFFFFFFFFu, v, o));
    return v;
}
__device__ __forceinline__ float warp_sum(float v) {
    #pragma unroll
    for (int o = 16; o; o >>= 1) v += __shfl_xor_sync(0xFFFFFFFFu, v, o);
    return v;
}

__device__ __forceinline__ float scinol_p(float p0, float S2, float G, float eta,
                                          float M, bool cond) {
    float denom = sqrtf(S2 + M * M);
    float theta = fminf(fmaxf(G / denom, -1.0f), 1.0f);
    float upd = cond ? theta / (2.0f * denom) * eta : 0.0f;
    return p0 + upd;
}

// Packed f32x2 FMA: d.lo += a.lo*b.lo ; d.hi += a.hi*b.hi  (Blackwell 2x FP32 path)
__device__ __forceinline__ void fma2(ull& d, ull a, ull b) {
    asm("fma.rn.f32x2 %0, %1, %2, %0;" : "+l"(d) : "l"(a), "l"(b));
}
__device__ __forceinline__ ull pack2(float lo, float hi) {
    return ((ull)__float_as_uint(hi) << 32) | (ull)__float_as_uint(lo);
}
__device__ __forceinline__ float unpack_lo(ull v) { return __uint_as_float((unsigned)v); }
__device__ __forceinline__ float unpack_hi(ull v) { return __uint_as_float((unsigned)(v >> 32)); }

// ---------------------------------------------------------------------------
// Stage 1: stat1 = mean_n( max_{h,w} |x[n,0,h,w]| )
// ---------------------------------------------------------------------------
__global__ void k_stat1_max(const float* __restrict__ x) {
    int n = blockIdx.x;
    const float* xp = x + (size_t)n * 784;
    float m = 0.0f;
    for (int i = threadIdx.x; i < 784; i += 256) m = fmaxf(m, fabsf(xp[i]));
    __shared__ float s[8];
    m = warp_max(m);
    if ((threadIdx.x & 31) == 0) s[threadIdx.x >> 5] = m;
    __syncthreads();
    if (threadIdx.x < 32) {
        float v = (threadIdx.x < 8) ? s[threadIdx.x] : 0.0f;
        v = warp_max(v);
        if (threadIdx.x == 0) g_smax1[n] = v;
    }
}

__global__ void k_stat1_mean() {
    float s = 0.0f;
    for (int i = threadIdx.x; i < 2048; i += 256) s += g_smax1[i];
    __shared__ float sm[8];
    s = warp_sum(s);
    if ((threadIdx.x & 31) == 0) sm[threadIdx.x >> 5] = s;
    __syncthreads();
    if (threadIdx.x < 32) {
        float v = (threadIdx.x < 8) ? sm[threadIdx.x] : 0.0f;
        v = warp_sum(v);
        if (threadIdx.x == 0) g_stat1 = v * (1.0f / 2048.0f);
    }
}

// ---------------------------------------------------------------------------
// Conv1 effective weights, packed over channel pairs: g_w1p[k*32+coP]
// ---------------------------------------------------------------------------
__global__ void k_w1(const float* __restrict__ w0, const float* __restrict__ wS2,
                     const float* __restrict__ wG, const float* __restrict__ weta,
                     const float* __restrict__ wM,
                     const float* __restrict__ b0, const float* __restrict__ bS2,
                     const float* __restrict__ bG, const float* __restrict__ beta) {
    float M = fmaxf(g_stat1, wM[0]);
    int tot = gridDim.x * blockDim.x;
    int gid = blockIdx.x * blockDim.x + threadIdx.x;
    for (int p = gid; p < 800; p += tot) {
        int k = p >> 5, coP = p & 31;
        int iL = (2 * coP) * 25 + k;
        int iH = (2 * coP + 1) * 25 + k;
        float lo = scinol_p(w0[iL], wS2[iL], wG[iL], weta[iL], M, wG[iL] != 0.0f);
        float hi = scinol_p(w0[iH], wS2[iH], wG[iH], weta[iH], M, wG[iH] != 0.0f);
        g_w1p[p] = pack2(lo, hi);
    }
    for (int i = gid; i < 64; i += tot)
        g_b1[i] = scinol_p(b0[i], bS2[i], bG[i], beta[i], 1.0f, bG[i] != 0.0f);
}

// ---------------------------------------------------------------------------
// Conv1 + ReLU + 2x2 maxpool, f32x2 packed over output-channel pairs.
// 128 threads: coP = tid>>2 (co = 2*coP, 2*coP+1), quad q = tid&3 owns 9 of
// the 36 4x4 conv tiles. x held in smem as duplicated pairs (v,v).
// ---------------------------------------------------------------------------
__global__ void __launch_bounds__(128, 3) k_conv1(const float* __restrict__ x) {
    __shared__ ull xs2[784];   // 6.3 KB, (v,v) pairs
    int n = blockIdx.x;
    int tid = threadIdx.x;
    const float* xp = x + (size_t)n * 784;
    for (int i = tid; i < 784; i += 128) {
        float v = xp[i];
        xs2[i] = pack2(v, v);
    }
    __syncthreads();

    int coP = tid >> 2, q = tid & 3;
    float bL = g_b1[2 * coP], bH = g_b1[2 * coP + 1];
    float cmaxL = 0.0f, cmaxH = 0.0f;
    float* outL = g_pool1 + ((size_t)n * 64 + 2 * coP) * 144;
    float* outH = outL + 144;

    for (int t = q; t < 36; t += 4) {
        int tr = t / 6, tc = t - tr * 6;
        const ull* xc = xs2 + (tr * 4) * 28 + tc * 4;
        ull X[4][8];
        #pragma unroll
        for (int r = 0; r < 4; r++)
            #pragma unroll
            for (int c = 0; c < 8; c++)
                X[r][c] = xc[r * 28 + c];
        ull acc[4][4];
        #pragma unroll
        for (int i = 0; i < 4; i++)
            #pragma unroll
            for (int j = 0; j < 4; j++) acc[i][j] = 0ULL;

        #pragma unroll
        for (int ky = 0; ky < 5; ky++) {
            ull w[5];
            #pragma unroll
            for (int kx = 0; kx < 5; kx++)
                w[kx] = g_w1p[(ky * 5 + kx) * 32 + coP];
            #pragma unroll
            for (int kx = 0; kx < 5; kx++)
                #pragma unroll
                for (int i = 0; i < 4; i++)
                    #pragma unroll
                    for (int j = 0; j < 4; j++)
                        fma2(acc[i][j], w[kx], X[(ky + i) & 3][j + kx]);
            if (ky < 4) {
                #pragma unroll
                for (int c = 0; c < 8; c++)
                    X[ky & 3][c] = xc[(ky + 4) * 28 + c];
            }
        }

        #pragma unroll
        for (int pi = 0; pi < 2; pi++)
            #pragma unroll
            for (int pj = 0; pj < 2; pj++) {
                float mL = fmaxf(fmaxf(unpack_lo(acc[2*pi][2*pj]),   unpack_lo(acc[2*pi][2*pj+1])),
                                 fmaxf(unpack_lo(acc[2*pi+1][2*pj]), unpack_lo(acc[2*pi+1][2*pj+1])));
                float mH = fmaxf(fmaxf(unpack_hi(acc[2*pi][2*pj]),   unpack_hi(acc[2*pi][2*pj+1])),
                                 fmaxf(unpack_hi(acc[2*pi+1][2*pj]), unpack_hi(acc[2*pi+1][2*pj+1])));
                float vL = fmaxf(mL + bL, 0.0f);
                float vH = fmaxf(mH + bH, 0.0f);
                int off = (tr * 2 + pi) * 12 + (tc * 2 + pj);
                outL[off] = vL;
                outH[off] = vH;
                cmaxL = fmaxf(cmaxL, vL);
                cmaxH = fmaxf(cmaxH, vH);
            }
    }
    // reduce channel max over the 4 quads (adjacent lanes)
    cmaxL = fmaxf(cmaxL, __shfl_xor_sync(0xFFFFFFFFu, cmaxL, 1));
    cmaxL = fmaxf(cmaxL, __shfl_xor_sync(0xFFFFFFFFu, cmaxL, 2));
    cmaxH = fmaxf(cmaxH, __shfl_xor_sync(0xFFFFFFFFu, cmaxH, 1));
    cmaxH = fmaxf(cmaxH, __shfl_xor_sync(0xFFFFFFFFu, cmaxH, 2));
    if (q == 0) {
        g_max2[n * 64 + 2 * coP] = cmaxL;
        g_max2[n * 64 + 2 * coP + 1] = cmaxH;
    }
}

// ---------------------------------------------------------------------------
// stat2[c] = mean_n g_max2[n][c]
// ---------------------------------------------------------------------------
__global__ void k_stat2() {
    int c = blockIdx.x;
    float s = 0.0f;
    for (int i = threadIdx.x; i < 2048; i += 256) s += g_max2[i * 64 + c];
    __shared__ float sm[8];
    s = warp_sum(s);
    if ((threadIdx.x & 31) == 0) sm[threadIdx.x >> 5] = s;
    __syncthreads();
    if (threadIdx.x < 32) {
        float v = (threadIdx.x < 8) ? sm[threadIdx.x] : 0.0f;
        v = warp_sum(v);
        if (threadIdx.x == 0) g_stat2[c] = v * (1.0f / 2048.0f);
    }
}

// ---------------------------------------------------------------------------
// Conv2 effective weights, packed: g_w2p[(ci*25+k)*32 + coP]
// ---------------------------------------------------------------------------
__global__ void k_w2(const float* __restrict__ w0, const float* __restrict__ wS2,
                     const float* __restrict__ wG, const float* __restrict__ weta,
                     const float* __restrict__ wM,
                     const float* __restrict__ b0, const float* __restrict__ bS2,
                     const float* __restrict__ bG, const float* __restrict__ beta) {
    int tot = gridDim.x * blockDim.x;
    int gid = blockIdx.x * blockDim.x + threadIdx.x;
    for (int p = gid; p < 51200; p += tot) {
        int coP = p & 31;
        int t = p >> 5;
        int k = t % 25, ci = t / 25;
        float M = fmaxf(g_stat2[ci], wM[ci]);
        int iL = ((2 * coP) * 64 + ci) * 25 + k;
        int iH = ((2 * coP + 1) * 64 + ci) * 25 + k;
        float lo = scinol_p(w0[iL], wS2[iL], wG[iL], weta[iL], M, wG[iL] != 0.0f);
        float hi = scinol_p(w0[iH], wS2[iH], wG[iH], weta[iH], M, wG[iH] != 0.0f);
        g_w2p[p] = pack2(lo, hi);
    }
    for (int i = gid; i < 64; i += tot)
        g_b2[i] = scinol_p(b0[i], bS2[i], bG[i], beta[i], 1.0f, bG[i] != 0.0f);
}

// ---------------------------------------------------------------------------
// Conv2 + ReLU + 2x2 maxpool, f32x2 packed over output-channel pairs.
// Block = one sample; dynamic smem holds the whole 64x12x12 input plane as
// duplicated (v,v) pairs (72 KB). 128 threads: coP = tid>>2, quad = tid&3
// covers a 4x4 conv tile. Sliding 4-row register window per input channel.
// ---------------------------------------------------------------------------
__global__ void __launch_bounds__(128, 3) k_conv2() {
    extern __shared__ ull xs2[];   // 9216 pairs = 72 KB
    int n = blockIdx.x;
    int tid = threadIdx.x;
    const float* src = g_pool1 + (size_t)n * 9216;
    for (int i = tid; i < 9216; i += 128) {
        float v = src[i];
        xs2[i] = pack2(v, v);
    }
    __syncthreads();

    int coP = tid >> 2, q = tid & 3;
    int ty = q >> 1, tx = q & 1;
    ull acc[4][4];
    #pragma unroll
    for (int i = 0; i < 4; i++)
        #pragma unroll
        for (int j = 0; j < 4; j++) acc[i][j] = 0ULL;

    const ull* xbase = xs2 + (ty * 4) * 12 + tx * 4;
    const ull* wbase = g_w2p + coP;

    for (int ci = 0; ci < 64; ci++) {
        const ull* xc = xbase + ci * 144;
        const ull* wc = wbase + ci * 25 * 32;
        ull X[4][8];
        #pragma unroll
        for (int r = 0; r < 4; r++)
            #pragma unroll
            for (int c = 0; c < 8; c++)
                X[r][c] = xc[r * 12 + c];

        #pragma unroll
        for (int ky = 0; ky < 5; ky++) {
            ull w[5];
            #pragma unroll
            for (int kx = 0; kx < 5; kx++)
                w[kx] = __ldg(wc + (ky * 5 + kx) * 32);
            #pragma unroll
            for (int kx = 0; kx < 5; kx++)
                #pragma unroll
                for (int i = 0; i < 4; i++)
                    #pragma unroll
                    for (int j = 0; j < 4; j++)
                        fma2(acc[i][j], w[kx], X[(ky + i) & 3][j + kx]);
            if (ky < 4) {
                #pragma unroll
                for (int c = 0; c < 8; c++)
                    X[ky & 3][c] = xc[(ky + 4) * 12 + c];
            }
        }
    }

    float bL = __ldg(g_b2 + 2 * coP), bH = __ldg(g_b2 + 2 * coP + 1);
    float* outp = g_pool2 + (size_t)n * 1024;
    #pragma unroll
    for (int pi = 0; pi < 2; pi++)
        #pragma unroll
        for (int pj = 0; pj < 2; pj++) {
            float mL = fmaxf(fmaxf(unpack_lo(acc[2*pi][2*pj]),   unpack_lo(acc[2*pi][2*pj+1])),
                             fmaxf(unpack_lo(acc[2*pi+1][2*pj]), unpack_lo(acc[2*pi+1][2*pj+1])));
            float mH = fmaxf(fmaxf(unpack_hi(acc[2*pi][2*pj]),   unpack_hi(acc[2*pi][2*pj+1])),
                             fmaxf(unpack_hi(acc[2*pi+1][2*pj]), unpack_hi(acc[2*pi+1][2*pj+1])));
            float vL = fmaxf(mL + bL, 0.0f);
            float vH = fmaxf(mH + bH, 0.0f);
            int py = ty * 2 + pi, px = tx * 2 + pj;
            outp[(2 * coP) * 16 + py * 4 + px] = vL;
            outp[(2 * coP + 1) * 16 + py * 4 + px] = vH;
        }
}

// ---------------------------------------------------------------------------
// stat3[f] = mean_n pool2[n][f]   (values >= 0, |.| is identity)
// ---------------------------------------------------------------------------
__global__ void k_stat3() {
    int f = blockIdx.x * 32 + threadIdx.x;
    float s = 0.0f;
    for (int nidx = threadIdx.y; nidx < 2048; nidx += 8)
        s += g_pool2[(size_t)nidx * 1024 + f];
    __shared__ float sm[8][32];
    sm[threadIdx.y][threadIdx.x] = s;
    __syncthreads();
    if (threadIdx.y == 0) {
        float tot = 0.0f;
        #pragma unroll
        for (int r = 0; r < 8; r++) tot += sm[r][threadIdx.x];
        g_stat3[f] = tot * (1.0f / 2048.0f);
    }
}

// ---------------------------------------------------------------------------
// Linear effective weights (cond is wS2!=0 / bS2!=0; M = max(wM, stat3[f]))
// ---------------------------------------------------------------------------
__global__ void k_w3(const float* __restrict__ w0, const float* __restrict__ wS2,
                     const float* __restrict__ wG, const float* __restrict__ weta,
                     const float* __restrict__ wM,
                     const float* __restrict__ b0, const float* __restrict__ bS2,
                     const float* __restrict__ bG, const float* __restrict__ beta) {
    int tot = gridDim.x * blockDim.x;
    int gid = blockIdx.x * blockDim.x + threadIdx.x;
    for (int i = gid; i < 10240; i += tot) {
        int f = i & 1023;
        float M = fmaxf(wM[i], g_stat3[f]);
        g_w3[i] = scinol_p(w0[i], wS2[i], wG[i], weta[i], M, wS2[i] != 0.0f);
    }
    for (int i = gid; i < 10; i += tot)
        g_b3[i] = scinol_p(b0[i], bS2[i], bG[i], beta[i], 1.0f, bS2[i] != 0.0f);
}

// ---------------------------------------------------------------------------
// Linear: out[n][o] = pool2[n] . w3[o] + b3[o]. Block = sample, warp = output.
// ---------------------------------------------------------------------------
__global__ void __launch_bounds__(320) k_linear(float* __restrict__ out) {
    __shared__ float hs[1024];
    int n = blockIdx.x;
    int tid = threadIdx.x;
    const float* src = g_pool2 + (size_t)n * 1024;
    for (int i = tid; i < 1024; i += 320) hs[i] = src[i];
    __syncthreads();
    int w = tid >> 5, lane = tid & 31;
    const float* wr = g_w3 + w * 1024;
    float s = 0.0f;
    #pragma unroll 8
    for (int k = lane; k < 1024; k += 32) s = fmaf(hs[k], wr[k], s);
    s = warp_sum(s);
    if (lane == 0) out[n * 10 + w] = s + g_b3[w];
}

// ---------------------------------------------------------------------------
// Launch
// ---------------------------------------------------------------------------
extern "C" void kernel_launch(void* const* d_in, const int* in_sizes, int n_in,
                              void* d_out, int out_size) {
    const float* x = (const float*)d_in[0];
    const float* c1_w0 = (const float*)d_in[1];
    const float* c1_wS2 = (const float*)d_in[2];
    const float* c1_wG = (const float*)d_in[3];
    const float* c1_weta = (const float*)d_in[4];
    const float* c1_wM = (const float*)d_in[5];
    const float* c1_b0 = (const float*)d_in[6];
    const float* c1_bS2 = (const float*)d_in[7];
    const float* c1_bG = (const float*)d_in[8];
    const float* c1_beta = (const float*)d_in[9];
    const float* c2_w0 = (const float*)d_in[10];
    const float* c2_wS2 = (const float*)d_in[11];
    const float* c2_wG = (const float*)d_in[12];
    const float* c2_weta = (const float*)d_in[13];
    const float* c2_wM = (const float*)d_in[14];
    const float* c2_b0 = (const float*)d_in[15];
    const float* c2_bS2 = (const float*)d_in[16];
    const float* c2_bG = (const float*)d_in[17];
    const float* c2_beta = (const float*)d_in[18];
    const float* l_w0 = (const float*)d_in[19];
    const float* l_wS2 = (const float*)d_in[20];
    const float* l_wG = (const float*)d_in[21];
    const float* l_weta = (const float*)d_in[22];
    const float* l_wM = (const float*)d_in[23];
    const float* l_b0 = (const float*)d_in[24];
    const float* l_bS2 = (const float*)d_in[25];
    const float* l_bG = (const float*)d_in[26];
    const float* l_beta = (const float*)d_in[27];
    float* out = (float*)d_out;

    // 72 KB dynamic smem for conv2 (idempotent; host-side, not a stream op)
    cudaFuncSetAttribute(k_conv2, cudaFuncAttributeMaxDynamicSharedMemorySize, 73728);

    k_stat1_max<<<2048, 256>>>(x);
    k_stat1_mean<<<1, 256>>>();
    k_w1<<<8, 256>>>(c1_w0, c1_wS2, c1_wG, c1_weta, c1_wM, c1_b0, c1_bS2, c1_bG, c1_beta);
    k_conv1<<<2048, 128>>>(x);
    k_stat2<<<64, 256>>>();
    k_w2<<<128, 256>>>(c2_w0, c2_wS2, c2_wG, c2_weta, c2_wM, c2_b0, c2_bS2, c2_bG, c2_beta);
    k_conv2<<<2048, 128, 73728>>>();
    k_stat3<<<32, dim3(32, 8)>>>();
    k_w3<<<48, 256>>>(l_w0, l_wS2, l_wG, l_weta, l_wM, l_b0, l_bS2, l_bG, l_beta);
    k_linear<<<2048, 320>>>(out);
}